// round 8
// baseline (speedup 1.0000x reference)
#include <cuda_runtime.h>
#include <math.h>

#define N_NODES 100000
#define N_EDGES 6400000
#define F_IN    128
#define F_OUT   16

// ------------- device scratch (zero-init; invariants restored per call) ---
__device__ int   g_deg [N_NODES];            // in-deg from 0; gemm resets
__device__ float g_dinv[N_NODES];            // rsqrt(deg+1), written by gemm
__device__ float g_g   [N_NODES * F_OUT];    // dinv[n] * (x[n] @ W)
__device__ float g_acc [N_NODES * F_OUT];    // scatter acc; zeroed by deginit

// ---------------- K1: fused degree-count + state reset ---------------------
// Blocks [0, DEG_BLOCKS) count in-degrees (atomic floor ~27us);
// blocks [DEG_BLOCKS, +INIT_BLOCKS) stream-zero acc and out (hidden under it).
#define DEG_BLOCKS  25000                    // 25000*256 = N_EDGES
#define INIT_BLOCKS 1563                     // 1563*256 >= 400000 acc quads

__global__ void __launch_bounds__(256) k_deginit(const int* __restrict__ dst,
                                                 float* __restrict__ out) {
    if (blockIdx.x < DEG_BLOCKS) {
        int e = blockIdx.x * 256 + threadIdx.x;
        if (e < N_EDGES) atomicAdd(&g_deg[dst[e]], 1);
    } else {
        int i = (blockIdx.x - DEG_BLOCKS) * 256 + threadIdx.x;
        if (i < N_NODES * F_OUT / 4)
            ((float4*)g_acc)[i] = make_float4(0.f, 0.f, 0.f, 0.f);
        if (i < F_OUT) out[i] = 0.0f;
    }
}

// ---------------- K2: g[n] = rsqrt(deg[n]+1) * (x[n] @ W) ------------------
// R7 staged shape (coalesced smem staging), plus: stores dinv, resets deg.
#define GEMM_TPB   128
#define GEMM_NODES 128
#define ROW_PAD    132   // 528B rows, 16B-aligned, max 4-way LDS conflict

__global__ void __launch_bounds__(GEMM_TPB) k_gemm(const float* __restrict__ x,
                                                   const float* __restrict__ W) {
    extern __shared__ float sm[];
    float* sx = sm;                                // [GEMM_NODES][ROW_PAD]
    float* sw = sm + GEMM_NODES * ROW_PAD;         // [F_IN*F_OUT]

    for (int i = threadIdx.x; i < F_IN * F_OUT / 4; i += GEMM_TPB)
        ((float4*)sw)[i] = ((const float4*)W)[i];

    int base = blockIdx.x * GEMM_NODES;
    int tile_f4 = min(GEMM_NODES, N_NODES - base) * (F_IN / 4);
    const float4* xg = (const float4*)(x + (size_t)base * F_IN);
    for (int i = threadIdx.x; i < tile_f4; i += GEMM_TPB) {
        float4 v = xg[i];
        int row = i >> 5;
        int c4  = i & 31;
        *(float4*)(sx + row * ROW_PAD + c4 * 4) = v;
    }
    __syncthreads();

    int t = threadIdx.x;
    int n = base + t;
    if (n >= N_NODES) return;

    const float4* xr = (const float4*)(sx + t * ROW_PAD);
    float acc[F_OUT];
#pragma unroll
    for (int f = 0; f < F_OUT; f++) acc[f] = 0.f;

#pragma unroll
    for (int k4 = 0; k4 < F_IN / 4; k4++) {
        float4 xv = xr[k4];
        int k = k4 * 4;
#pragma unroll
        for (int f = 0; f < F_OUT; f++) {
            acc[f] += xv.x * sw[(k + 0) * F_OUT + f];
            acc[f] += xv.y * sw[(k + 1) * F_OUT + f];
            acc[f] += xv.z * sw[(k + 2) * F_OUT + f];
            acc[f] += xv.w * sw[(k + 3) * F_OUT + f];
        }
    }
    float dinv = rsqrtf((float)(g_deg[n] + 1));    // +1 self loop
    g_dinv[n] = dinv;
    g_deg[n] = 0;                                  // restore replay invariant
    float4* gg = (float4*)(g_g + (size_t)n * F_OUT);
#pragma unroll
    for (int q = 0; q < 4; q++) {
        gg[q] = make_float4(acc[q * 4 + 0] * dinv, acc[q * 4 + 1] * dinv,
                            acc[q * 4 + 2] * dinv, acc[q * 4 + 3] * dinv);
    }
}

#define GEMM_SMEM ((GEMM_NODES * ROW_PAD + F_IN * F_OUT) * (int)sizeof(float))

// ---------------- K3: scatter g[src] into acc[dst] (R2-proven, at floor) ---
__global__ void __launch_bounds__(256) k_scatter(const int* __restrict__ src,
                                                 const int* __restrict__ dst) {
    long long t = (long long)blockIdx.x * blockDim.x + threadIdx.x;
    int e = (int)(t >> 2);
    int q = (int)(t & 3);
    if (e >= N_EDGES) return;
    int r = src[e];
    int c = dst[e];
    float4 v = ((const float4*)g_g)[r * 4 + q];
    float* p = g_acc + (size_t)c * F_OUT + q * 4;
    asm volatile("red.global.add.v4.f32 [%0], {%1,%2,%3,%4};"
                 :: "l"(p), "f"(v.x), "f"(v.y), "f"(v.z), "f"(v.w)
                 : "memory");
}

// ---------------- K4: out = mean_n tanh(dinv*(acc+g) + b) (R2 shape) -------
__global__ void __launch_bounds__(256) k_finalize(const float* __restrict__ b,
                                                  float* __restrict__ out) {
    float bb[F_OUT];
#pragma unroll
    for (int f = 0; f < F_OUT; f++) bb[f] = b[f];

    float local[F_OUT];
#pragma unroll
    for (int f = 0; f < F_OUT; f++) local[f] = 0.f;

    const float invN = 1.0f / (float)N_NODES;
    for (int n = blockIdx.x * blockDim.x + threadIdx.x; n < N_NODES;
         n += gridDim.x * blockDim.x) {
        float dinv = g_dinv[n];
        const float4* a4 = (const float4*)(g_acc + (size_t)n * F_OUT);
        const float4* g4 = (const float4*)(g_g + (size_t)n * F_OUT);
#pragma unroll
        for (int q = 0; q < 4; q++) {
            float4 a = a4[q];
            float4 g = g4[q];
            local[q * 4 + 0] += tanhf(dinv * (a.x + g.x) + bb[q * 4 + 0]);
            local[q * 4 + 1] += tanhf(dinv * (a.y + g.y) + bb[q * 4 + 1]);
            local[q * 4 + 2] += tanhf(dinv * (a.z + g.z) + bb[q * 4 + 2]);
            local[q * 4 + 3] += tanhf(dinv * (a.w + g.w) + bb[q * 4 + 3]);
        }
    }

#pragma unroll
    for (int off = 16; off > 0; off >>= 1) {
#pragma unroll
        for (int f = 0; f < F_OUT; f++)
            local[f] += __shfl_xor_sync(0xFFFFFFFFu, local[f], off);
    }
    int lane = threadIdx.x & 31;
    if (lane < F_OUT) {
        atomicAdd(&out[lane], local[lane] * invN);
    }
}

// ---------------- launch ---------------------------------------------------
extern "C" void kernel_launch(void* const* d_in, const int* in_sizes, int n_in,
                              void* d_out, int out_size) {
    const float* x  = (const float*)d_in[0];
    const int*   ei = (const int*)d_in[1];   // [2, N_EDGES] int32 (JAX x64 off)
    const float* W  = (const float*)d_in[2];
    const float* b  = (const float*)d_in[3];
    float*       out = (float*)d_out;

    const int* src = ei;              // edge_index[0]
    const int* dst = ei + N_EDGES;    // edge_index[1]

    cudaFuncSetAttribute(k_gemm, cudaFuncAttributeMaxDynamicSharedMemorySize,
                         GEMM_SMEM);

    k_deginit<<<DEG_BLOCKS + INIT_BLOCKS, 256>>>(dst, out);
    {
        int blocks = (N_NODES + GEMM_NODES - 1) / GEMM_NODES;
        k_gemm<<<blocks, GEMM_TPB, GEMM_SMEM>>>(x, W);
    }
    {
        long long threads = (long long)N_EDGES * 4;
        k_scatter<<<(int)((threads + 255) / 256), 256>>>(src, dst);
    }
    k_finalize<<<592, 256>>>(b, out);
}

// round 9
// speedup vs baseline: 1.0477x; 1.0477x over previous
#include <cuda_runtime.h>
#include <math.h>

#define N_NODES 100000
#define N_EDGES 6400000
#define F_IN    128
#define F_OUT   16

// ------------- device scratch (zero-init; invariants restored per call) ---
__device__ int   g_deg [N_NODES];            // in-deg from 0; k_dinv resets
__device__ float g_dinv[N_NODES];            // rsqrt(deg+1)
__device__ float g_g   [N_NODES * F_OUT];    // h=x@W (unscaled), then *dinv
__device__ float g_acc [N_NODES * F_OUT];    // scatter acc; zeroed in fused

// ---------------- K1: fused  gemm(h) || degree || zero ---------------------
// Roles interleaved by blockIdx%5 so all three are co-resident:
//   %5 in {0,1} -> gemm   (782 ids, 128 nodes each, R2-proven inner loop)
//   %5 in {2,3} -> degree (782 ids, grid-stride, fire-and-forget REDG)
//   %5 == 4     -> zero   (391 ids, stream-zero acc + out)
#define GEMM_IDS 782
#define DEG_IDS  782
#define ZERO_IDS 391
#define FUSED_BLOCKS (GEMM_IDS + DEG_IDS + ZERO_IDS)   // 1955
#define DEG_STRIDE (DEG_IDS * 128)                      // 100096 threads

__global__ void __launch_bounds__(128) k_fused(const float* __restrict__ x,
                                               const float* __restrict__ W,
                                               const int* __restrict__ dst,
                                               float* __restrict__ out) {
    __shared__ float Ws[F_IN * F_OUT];
    int role = blockIdx.x % 5;
    int gid  = blockIdx.x / 5;
    int tid  = threadIdx.x;

    if (role < 2) {                            // ---- GEMM role ----
        int gemm_id = gid * 2 + role;          // 0..781
        for (int i = tid; i < F_IN * F_OUT; i += 128) Ws[i] = W[i];
        __syncthreads();

        int n = gemm_id * 128 + tid;
        if (n >= N_NODES) return;

        const float4* x4 = (const float4*)(x + (size_t)n * F_IN);
        float acc[F_OUT];
#pragma unroll
        for (int f = 0; f < F_OUT; f++) acc[f] = 0.f;

#pragma unroll
        for (int k4 = 0; k4 < F_IN / 4; k4++) {
            float4 xv = x4[k4];
            int k = k4 * 4;
#pragma unroll
            for (int f = 0; f < F_OUT; f++) {
                acc[f] += xv.x * Ws[(k + 0) * F_OUT + f];
                acc[f] += xv.y * Ws[(k + 1) * F_OUT + f];
                acc[f] += xv.z * Ws[(k + 2) * F_OUT + f];
                acc[f] += xv.w * Ws[(k + 3) * F_OUT + f];
            }
        }
        float4* gg = (float4*)(g_g + (size_t)n * F_OUT);
#pragma unroll
        for (int q = 0; q < 4; q++)
            gg[q] = make_float4(acc[q * 4 + 0], acc[q * 4 + 1],
                                acc[q * 4 + 2], acc[q * 4 + 3]);
    } else if (role < 4) {                     // ---- DEGREE role ----
        int deg_id = gid * 2 + (role - 2);     // 0..781
        int e = deg_id * 128 + tid;
#pragma unroll 4
        for (; e < N_EDGES; e += DEG_STRIDE) {
            int c = dst[e];
            atomicAdd(&g_deg[c], 1);           // REDG: fire-and-forget
        }
    } else {                                   // ---- ZERO role ----
        const float4 z4 = make_float4(0.f, 0.f, 0.f, 0.f);
        for (int i = gid * 128 + tid; i < N_NODES * F_OUT / 4;
             i += ZERO_IDS * 128)
            ((float4*)g_acc)[i] = z4;
        if (gid == 0 && tid < F_OUT) out[tid] = 0.0f;
    }
}

// ---------------- K2: dinv = rsqrt(deg+1); g *= dinv; reset deg ------------
__global__ void __launch_bounds__(256) k_dinv() {
    int n = blockIdx.x * 256 + threadIdx.x;
    if (n < N_NODES) {
        float dv = rsqrtf((float)(g_deg[n] + 1));   // +1 self loop
        g_dinv[n] = dv;
        g_deg[n] = 0;                          // restore invariant for replay
        float4* gg = (float4*)(g_g + (size_t)n * F_OUT);
#pragma unroll
        for (int q = 0; q < 4; q++) {
            float4 v = gg[q];
            gg[q] = make_float4(v.x * dv, v.y * dv, v.z * dv, v.w * dv);
        }
    }
}

// ---------------- K3: scatter g[src] into acc[dst] (R2-proven, at floor) ---
__global__ void __launch_bounds__(256) k_scatter(const int* __restrict__ src,
                                                 const int* __restrict__ dst) {
    long long t = (long long)blockIdx.x * blockDim.x + threadIdx.x;
    int e = (int)(t >> 2);
    int q = (int)(t & 3);
    if (e >= N_EDGES) return;
    int r = src[e];
    int c = dst[e];
    float4 v = ((const float4*)g_g)[r * 4 + q];
    float* p = g_acc + (size_t)c * F_OUT + q * 4;
    asm volatile("red.global.add.v4.f32 [%0], {%1,%2,%3,%4};"
                 :: "l"(p), "f"(v.x), "f"(v.y), "f"(v.z), "f"(v.w)
                 : "memory");
}

// ---------------- K4: out = mean_n tanh(dinv*(acc+g) + b) (proven 11.6us) --
__global__ void __launch_bounds__(256) k_finalize(const float* __restrict__ b,
                                                  float* __restrict__ out) {
    float bb[F_OUT];
#pragma unroll
    for (int f = 0; f < F_OUT; f++) bb[f] = b[f];

    float local[F_OUT];
#pragma unroll
    for (int f = 0; f < F_OUT; f++) local[f] = 0.f;

    const float invN = 1.0f / (float)N_NODES;
    for (int n = blockIdx.x * blockDim.x + threadIdx.x; n < N_NODES;
         n += gridDim.x * blockDim.x) {
        float dinv = g_dinv[n];
        const float4* a4 = (const float4*)(g_acc + (size_t)n * F_OUT);
        const float4* g4 = (const float4*)(g_g + (size_t)n * F_OUT);
#pragma unroll
        for (int q = 0; q < 4; q++) {
            float4 a = a4[q];
            float4 g = g4[q];
            local[q * 4 + 0] += tanhf(dinv * (a.x + g.x) + bb[q * 4 + 0]);
            local[q * 4 + 1] += tanhf(dinv * (a.y + g.y) + bb[q * 4 + 1]);
            local[q * 4 + 2] += tanhf(dinv * (a.z + g.z) + bb[q * 4 + 2]);
            local[q * 4 + 3] += tanhf(dinv * (a.w + g.w) + bb[q * 4 + 3]);
        }
    }

#pragma unroll
    for (int off = 16; off > 0; off >>= 1) {
#pragma unroll
        for (int f = 0; f < F_OUT; f++)
            local[f] += __shfl_xor_sync(0xFFFFFFFFu, local[f], off);
    }
    int lane = threadIdx.x & 31;
    if (lane < F_OUT) {
        atomicAdd(&out[lane], local[lane] * invN);
    }
}

// ---------------- launch ---------------------------------------------------
extern "C" void kernel_launch(void* const* d_in, const int* in_sizes, int n_in,
                              void* d_out, int out_size) {
    const float* x  = (const float*)d_in[0];
    const int*   ei = (const int*)d_in[1];   // [2, N_EDGES] int32 (JAX x64 off)
    const float* W  = (const float*)d_in[2];
    const float* b  = (const float*)d_in[3];
    float*       out = (float*)d_out;

    const int* src = ei;              // edge_index[0]
    const int* dst = ei + N_EDGES;    // edge_index[1]

    k_fused<<<FUSED_BLOCKS, 128>>>(x, W, dst, out);
    k_dinv <<<(N_NODES + 255) / 256, 256>>>();
    {
        long long threads = (long long)N_EDGES * 4;
        k_scatter<<<(int)((threads + 255) / 256), 256>>>(src, dst);
    }
    k_finalize<<<592, 256>>>(b, out);
}